// round 14
// baseline (speedup 1.0000x reference)
#include <cuda_runtime.h>
#include <cuda_bf16.h>
#include <cuda_fp16.h>
#include <math.h>
#include <stdint.h>

#define NMAX 100000
#define EMAX 1600000
#define F 128
#define NB_MAX 782

// ---------------- scratch (device globals) ----------------------------------
__device__ int   g_cnt[NMAX];            // zeroed invariant: k_offsets re-zeroes
__device__ int   g_off[NMAX];
__device__ int   g_end[NMAX];
__device__ int   g_pos[NMAX];
__device__ int   g_total;
__device__ int   g_srcs[EMAX];
__device__ int   g_eidx[EMAX];
__device__ float g_deg[NMAX];
__device__ float g_agg[(size_t)NMAX * F];
__device__ float g_h1[(size_t)NMAX * F];
__device__ __half g_h2h[(size_t)NMAX * F];   // layer-2 output, fp16 (score-only consumer)
__device__ unsigned int g_mm[2];

// W images per layer (128KB): [self_hi 32K][neigh_hi 32K][self_lo 32K][neigh_lo 32K]
__device__ uint8_t g_Wimg[2 * 4 * 32768];

// ---------------- helpers -----------------------------------------------------
__device__ __forceinline__ unsigned fenc(float f) {
    unsigned u = __float_as_uint(f);
    return (u & 0x80000000u) ? ~u : (u | 0x80000000u);
}
__device__ __forceinline__ float fdec(unsigned u) {
    return __uint_as_float((u & 0x80000000u) ? (u ^ 0x80000000u) : ~u);
}
__device__ __forceinline__ uint32_t pkf(float a, float b) {
    __nv_bfloat162 t = __floats2bfloat162_rn(a, b);
    return *(uint32_t*)&t;
}
__device__ __forceinline__ void split2(float a, float b, uint32_t& hi, uint32_t& lo) {
    __nv_bfloat16 ha = __float2bfloat16(a), hb = __float2bfloat16(b);
    __nv_bfloat162 h2 = __halves2bfloat162(ha, hb);
    hi = *(uint32_t*)&h2;
    lo = pkf(a - __bfloat162float(ha), b - __bfloat162float(hb));
}
__device__ __forceinline__ uint32_t smem_u32(const void* p) {
    uint32_t a;
    asm("{ .reg .u64 t; cvta.to.shared.u64 t, %1; cvt.u32.u64 %0, t; }" : "=r"(a) : "l"(p));
    return a;
}
__device__ __forceinline__ void mb_init(uint32_t m, uint32_t c) {
    asm volatile("mbarrier.init.shared.b64 [%0], %1;" :: "r"(m), "r"(c) : "memory");
}
__device__ __forceinline__ void mb_extx(uint32_t m, uint32_t bytes) {
    asm volatile("mbarrier.arrive.expect_tx.shared.b64 _, [%0], %1;" :: "r"(m), "r"(bytes) : "memory");
}
__device__ __forceinline__ void mb_wait(uint32_t m, uint32_t parity) {
    asm volatile(
        "{\n\t.reg .pred P;\n\t"
        "WL_%=: mbarrier.try_wait.parity.shared::cta.b64 P, [%0], %1;\n\t"
        "@P bra WD_%=;\n\t bra WL_%=;\n\tWD_%=:\n\t}"
        :: "r"(m), "r"(parity) : "memory");
}
__device__ __forceinline__ void bulk_g2s(uint32_t dst, const void* src, uint32_t bytes, uint32_t mbar) {
    asm volatile("cp.async.bulk.shared::cta.global.mbarrier::complete_tx::bytes [%0], [%1], %2, [%3];"
                 :: "r"(dst), "l"(src), "r"(bytes), "r"(mbar) : "memory");
}
__device__ __forceinline__ void mma_bf16(float* d, const uint4 a, const uint2 b) {
    asm volatile(
        "mma.sync.aligned.m16n8k16.row.col.f32.bf16.bf16.f32 "
        "{%0,%1,%2,%3}, {%4,%5,%6,%7}, {%8,%9}, {%0,%1,%2,%3};"
        : "+f"(d[0]), "+f"(d[1]), "+f"(d[2]), "+f"(d[3])
        : "r"(a.x), "r"(a.y), "r"(a.z), "r"(a.w), "r"(b.x), "r"(b.y));
}
// dot of 4 fp16 pairs (as uint2) in fp32
__device__ __forceinline__ float dot4h(uint2 a, uint2 b) {
    float2 ax = __half22float2(*(__half2*)&a.x);
    float2 ay = __half22float2(*(__half2*)&a.y);
    float2 bx = __half22float2(*(__half2*)&b.x);
    float2 by = __half22float2(*(__half2*)&b.y);
    return ax.x * bx.x + ax.y * bx.y + ay.x * by.x + ay.y * by.y;
}

// ---------------- CSR count + fused W conversion ------------------------------
__global__ void k_count(const int* __restrict__ dst, int e, int countBlocks,
                        const float* __restrict__ Ws1, const float* __restrict__ Wn1,
                        const float* __restrict__ Ws2, const float* __restrict__ Wn2) {
    if ((int)blockIdx.x >= countBlocks) {
        int idx = ((int)blockIdx.x - countBlocks) * blockDim.x + threadIdx.x;
        if (idx >= 4 * 8 * 16 * 32) return;
        int lane = idx & 31;
        int tn = (idx >> 5) & 15;
        int tk = (idx >> 9) & 7;
        int m = idx >> 12;
        const float* W = (m == 0) ? Ws1 : (m == 1) ? Wn1 : (m == 2) ? Ws2 : Wn2;
        int g = lane >> 2, t = lane & 3;
        int nn = tn * 8 + g;
        int k0 = tk * 16 + 2 * t;
        float w00 = __ldg(W + k0 * F + nn);
        float w01 = __ldg(W + (k0 + 1) * F + nn);
        float w10 = __ldg(W + (k0 + 8) * F + nn);
        float w11 = __ldg(W + (k0 + 9) * F + nn);
        uint2 hi, lo;
        split2(w00, w01, hi.x, lo.x);
        split2(w10, w11, hi.y, lo.y);
        int layer = m >> 1, which = m & 1;
        size_t base = (size_t)layer * 131072;
        size_t off = tk * 4096 + tn * 256 + lane * 8;
        *(uint2*)(g_Wimg + base + (size_t)which * 32768 + off) = hi;
        *(uint2*)(g_Wimg + base + 65536 + (size_t)which * 32768 + off) = lo;
        return;
    }
    if (threadIdx.x == 0 && blockIdx.x == 0) {
        g_total = 0;
        g_mm[0] = 0xFFFFFFFFu;
        g_mm[1] = 0u;
    }
    int i = blockIdx.x * blockDim.x + threadIdx.x;
    if (i < e) atomicAdd(&g_cnt[dst[i]], 1);
}

__global__ void k_offsets(int n) {
    __shared__ int wsum[8];
    __shared__ int sbase;
    int i = blockIdx.x * blockDim.x + threadIdx.x;
    int lane = threadIdx.x & 31, wid = threadIdx.x >> 5;
    int c = (i < n) ? g_cnt[i] : 0;
    int v = c;
#pragma unroll
    for (int o = 1; o < 32; o <<= 1) {
        int t = __shfl_up_sync(0xffffffffu, v, o);
        if (lane >= o) v += t;
    }
    if (lane == 31) wsum[wid] = v;
    __syncthreads();
    if (wid == 0) {
        int s = (lane < 8) ? wsum[lane] : 0;
#pragma unroll
        for (int o = 1; o < 8; o <<= 1) {
            int t = __shfl_up_sync(0xffffffffu, s, o);
            if (lane >= o) s += t;
        }
        if (lane < 8) wsum[lane] = s;
        if (lane == 7) sbase = atomicAdd(&g_total, s);
    }
    __syncthreads();
    if (i < n) {
        int excl = sbase + v - c + (wid ? wsum[wid - 1] : 0);
        g_off[i] = excl;
        g_pos[i] = excl;
        g_end[i] = excl + c;
        g_deg[i] = 1.0f / fmaxf((float)c, 1.0f);
        g_cnt[i] = 0;
    }
}

__global__ void k_fill(const int* __restrict__ src, const int* __restrict__ dst, int e) {
    int i = blockIdx.x * blockDim.x + threadIdx.x;
    if (i < e) {
        int p = atomicAdd(&g_pos[dst[i]], 1);
        g_srcs[p] = src[i];
        g_eidx[p] = i;
    }
}

// ---------------- gather: warp per node, 2-way unroll ------------------------
__global__ void k_gather(const float* __restrict__ h, int n) {
    int w = (blockIdx.x * blockDim.x + threadIdx.x) >> 5;
    if (w >= n) return;
    int lane = threadIdx.x & 31;
    int beg = g_off[w];
    int end = g_end[w];
    float4 acc = make_float4(0.f, 0.f, 0.f, 0.f);
    int j = beg;
    for (; j + 1 < end; j += 2) {
        int s0 = __ldg(g_srcs + j);
        int s1 = __ldg(g_srcs + j + 1);
        float4 v0 = __ldg((const float4*)h + (size_t)s0 * 32 + lane);
        float4 v1 = __ldg((const float4*)h + (size_t)s1 * 32 + lane);
        acc.x += v0.x + v1.x; acc.y += v0.y + v1.y;
        acc.z += v0.z + v1.z; acc.w += v0.w + v1.w;
    }
    if (j < end) {
        int s0 = __ldg(g_srcs + j);
        float4 v0 = __ldg((const float4*)h + (size_t)s0 * 32 + lane);
        acc.x += v0.x; acc.y += v0.y; acc.z += v0.z; acc.w += v0.w;
    }
    float inv = g_deg[w];
    acc.x *= inv; acc.y *= inv; acc.z *= inv; acc.w *= inv;
    ((float4*)g_agg)[(size_t)w * 32 + lane] = acc;
}

// ---------------- conv cell helpers ------------------------------------------
__device__ __forceinline__ void conv_load(const float* __restrict__ src, int n,
                                          int base_row, int idx,
                                          float2& a00, float2& a01, float2& a10, float2& a11) {
    int lane = idx & 31;
    int tk = (idx >> 5) & 7;
    int tm = idx >> 8;
    int g = lane >> 2, t = lane & 3;
    int row0 = base_row + tm * 16 + g;
    int row1 = row0 + 8;
    int k0 = tk * 16 + 2 * t;
    a00 = make_float2(0.f, 0.f); a01 = a00; a10 = a00; a11 = a00;
    if (row0 < n) {
        a00 = __ldg((const float2*)(src + (size_t)row0 * F + k0));
        a01 = __ldg((const float2*)(src + (size_t)row0 * F + k0 + 8));
    }
    if (row1 < n) {
        a10 = __ldg((const float2*)(src + (size_t)row1 * F + k0));
        a11 = __ldg((const float2*)(src + (size_t)row1 * F + k0 + 8));
    }
}
__device__ __forceinline__ void conv_store(uint8_t* As, int idx,
                                           float2 a00, float2 a01, float2 a10, float2 a11) {
    int lane = idx & 31;
    int tk = (idx >> 5) & 7;
    int tm = idx >> 8;
    uint4 hi, lo;
    split2(a00.x, a00.y, hi.x, lo.x);
    split2(a10.x, a10.y, hi.y, lo.y);
    split2(a01.x, a01.y, hi.z, lo.z);
    split2(a11.x, a11.y, hi.w, lo.w);
    uint32_t off = tm * 4096 + tk * 512 + lane * 16;
    *(uint4*)(As + off) = hi;
    *(uint4*)(As + 32768 + off) = lo;
}
__device__ __forceinline__ void conv_tile(const float* __restrict__ src, int n,
                                          int base_row, uint8_t* As, int tid) {
#pragma unroll
    for (int u = 0; u < 8; u++) {
        float2 a00, a01, a10, a11;
        conv_load(src, n, base_row, tid + u * 256, a00, a01, a10, a11);
        conv_store(As, tid + u * 256, a00, a01, a10, a11);
    }
}

// ---------------- mma.sync GEMM, fully fused ---------------------------------
// hout (fp32) for layer 1; houtH (fp16) for layer 2 (score consumer).
__global__ void __launch_bounds__(256, 1)
k_mma(const float* __restrict__ selfF, const float* __restrict__ neighF,
      const uint8_t* __restrict__ Wbase, const float* __restrict__ bias,
      float* __restrict__ hout, __half* __restrict__ houtH, int n) {
    extern __shared__ __align__(128) uint8_t sm[];
    const uint32_t WOFF = 1024, A0OFF = 1024 + 65536, A1OFF = A0OFF + 65536;
    const int tid = threadIdx.x;
    const int lane = tid & 31, wid = tid >> 5;
    const int warp_m = wid >> 2, warp_n = wid & 3;
    const size_t b = blockIdx.x;
    const int base_row = (int)b * 128;
    uint32_t sb = smem_u32(sm);

    if (tid == 0) {
        mb_init(sb + 0, 1);
        asm volatile("fence.proxy.async.shared::cta;" ::: "memory");
    }
    __syncthreads();
    if (tid == 0) {
        mb_extx(sb + 0, 65536);
        bulk_g2s(sb + WOFF, Wbase, 65536, sb + 0);       // self_hi + neigh_hi
    }
    conv_tile(selfF, n, base_row, sm + A0OFF, tid);
    __syncthreads();
    mb_wait(sb + 0, 0);

    const uint8_t* WhiS = sm + WOFF;
    const uint8_t* WhiN = sm + WOFF + 32768;
    const uint8_t* WloS = Wbase + 65536;                 // global, L2-hot
    const uint8_t* WloN = Wbase + 98304;

    float acc[4][4][4];
#pragma unroll
    for (int i = 0; i < 4; i++)
#pragma unroll
        for (int j = 0; j < 4; j++)
#pragma unroll
            for (int c = 0; c < 4; c++) acc[i][j][c] = 0.f;

    // ---- phase 0 (self), neigh conversion pipelined in ----
#pragma unroll
    for (int tk = 0; tk < 8; tk++) {
        float2 c00, c01, c10, c11;
        conv_load(neighF, n, base_row, tid + tk * 256, c00, c01, c10, c11);

        uint4 af[4];
#pragma unroll
        for (int i = 0; i < 4; i++)
            af[i] = *(const uint4*)(sm + A0OFF + (warp_m * 4 + i) * 4096 + tk * 512 + lane * 16);
        {
            uint2 bf[4];
#pragma unroll
            for (int j = 0; j < 4; j++)
                bf[j] = *(const uint2*)(WhiS + tk * 4096 + (warp_n * 4 + j) * 256 + lane * 8);
#pragma unroll
            for (int i = 0; i < 4; i++)
#pragma unroll
                for (int j = 0; j < 4; j++)
                    mma_bf16(acc[i][j], af[i], bf[j]);
        }
        {
            uint2 bf[4];
#pragma unroll
            for (int j = 0; j < 4; j++)
                bf[j] = __ldg((const uint2*)(WloS + tk * 4096 + (warp_n * 4 + j) * 256 + lane * 8));
#pragma unroll
            for (int i = 0; i < 4; i++)
#pragma unroll
                for (int j = 0; j < 4; j++)
                    mma_bf16(acc[i][j], af[i], bf[j]);
        }
        conv_store(sm + A1OFF, tid + tk * 256, c00, c01, c10, c11);
    }
    // lo(self) x Whi(self)
#pragma unroll
    for (int tk = 0; tk < 8; tk++) {
        uint4 af[4];
        uint2 bf[4];
#pragma unroll
        for (int i = 0; i < 4; i++)
            af[i] = *(const uint4*)(sm + A0OFF + 32768 + (warp_m * 4 + i) * 4096 + tk * 512 + lane * 16);
#pragma unroll
        for (int j = 0; j < 4; j++)
            bf[j] = *(const uint2*)(WhiS + tk * 4096 + (warp_n * 4 + j) * 256 + lane * 8);
#pragma unroll
        for (int i = 0; i < 4; i++)
#pragma unroll
            for (int j = 0; j < 4; j++)
                mma_bf16(acc[i][j], af[i], bf[j]);
    }

    __syncthreads();                                     // A1 complete

    // ---- phase 1 (neigh) ----
#pragma unroll
    for (int tk = 0; tk < 8; tk++) {
        uint4 af[4];
#pragma unroll
        for (int i = 0; i < 4; i++)
            af[i] = *(const uint4*)(sm + A1OFF + (warp_m * 4 + i) * 4096 + tk * 512 + lane * 16);
        {
            uint2 bf[4];
#pragma unroll
            for (int j = 0; j < 4; j++)
                bf[j] = *(const uint2*)(WhiN + tk * 4096 + (warp_n * 4 + j) * 256 + lane * 8);
#pragma unroll
            for (int i = 0; i < 4; i++)
#pragma unroll
                for (int j = 0; j < 4; j++)
                    mma_bf16(acc[i][j], af[i], bf[j]);
        }
        {
            uint2 bf[4];
#pragma unroll
            for (int j = 0; j < 4; j++)
                bf[j] = __ldg((const uint2*)(WloN + tk * 4096 + (warp_n * 4 + j) * 256 + lane * 8));
#pragma unroll
            for (int i = 0; i < 4; i++)
#pragma unroll
                for (int j = 0; j < 4; j++)
                    mma_bf16(acc[i][j], af[i], bf[j]);
        }
    }
#pragma unroll
    for (int tk = 0; tk < 8; tk++) {
        uint4 af[4];
        uint2 bf[4];
#pragma unroll
        for (int i = 0; i < 4; i++)
            af[i] = *(const uint4*)(sm + A1OFF + 32768 + (warp_m * 4 + i) * 4096 + tk * 512 + lane * 16);
#pragma unroll
        for (int j = 0; j < 4; j++)
            bf[j] = *(const uint2*)(WhiN + tk * 4096 + (warp_n * 4 + j) * 256 + lane * 8);
#pragma unroll
        for (int i = 0; i < 4; i++)
#pragma unroll
            for (int j = 0; j < 4; j++)
                mma_bf16(acc[i][j], af[i], bf[j]);
    }

    // ---- epilogue: bias + fp32 (layer 1) or fp16 (layer 2) out ----
    const int g = lane >> 2, t = lane & 3;
#pragma unroll
    for (int i = 0; i < 4; i++) {
        int tm = warp_m * 4 + i;
        int row0 = base_row + tm * 16 + g;
        int row1 = row0 + 8;
#pragma unroll
        for (int j = 0; j < 4; j++) {
            int nb8 = (warp_n * 4 + j) * 8 + 2 * t;
            float2 bv = __ldg((const float2*)(bias + nb8));
            float c0 = acc[i][j][0] + bv.x, c1 = acc[i][j][1] + bv.y;
            float c2 = acc[i][j][2] + bv.x, c3 = acc[i][j][3] + bv.y;
            if (hout) {
                if (row0 < n) *(float2*)(hout + (size_t)row0 * F + nb8) = make_float2(c0, c1);
                if (row1 < n) *(float2*)(hout + (size_t)row1 * F + nb8) = make_float2(c2, c3);
            } else {
                if (row0 < n) *(__half2*)(houtH + (size_t)row0 * F + nb8) = __floats2half2_rn(c0, c1);
                if (row1 < n) *(__half2*)(houtH + (size_t)row1 * F + nb8) = __floats2half2_rn(c2, c3);
            }
        }
    }
}

// ---------------- CSR edge scores on fp16 rows: warp per node ----------------
__global__ void k_score(const __half* __restrict__ h, float* __restrict__ out, int n) {
    int w = (blockIdx.x * blockDim.x + threadIdx.x) >> 5;
    int lane = threadIdx.x & 31;
    float lmin = 3.402823466e38f;
    float lmax = -3.402823466e38f;

    if (w < n) {
        int beg = g_off[w];
        int end = g_end[w];
        uint2 d4 = __ldg((const uint2*)h + (size_t)w * 32 + lane);   // 4 halves
        int j = beg;
        for (; j + 3 < end; j += 4) {
            int s0 = __ldg(g_srcs + j);
            int s1 = __ldg(g_srcs + j + 1);
            int s2 = __ldg(g_srcs + j + 2);
            int s3 = __ldg(g_srcs + j + 3);
            uint2 a0 = __ldg((const uint2*)h + (size_t)s0 * 32 + lane);
            uint2 a1 = __ldg((const uint2*)h + (size_t)s1 * 32 + lane);
            uint2 a2 = __ldg((const uint2*)h + (size_t)s2 * 32 + lane);
            uint2 a3 = __ldg((const uint2*)h + (size_t)s3 * 32 + lane);
            float p0 = dot4h(a0, d4);
            float p1 = dot4h(a1, d4);
            float p2 = dot4h(a2, d4);
            float p3 = dot4h(a3, d4);
#pragma unroll
            for (int o = 16; o; o >>= 1) {
                p0 += __shfl_xor_sync(0xffffffffu, p0, o);
                p1 += __shfl_xor_sync(0xffffffffu, p1, o);
                p2 += __shfl_xor_sync(0xffffffffu, p2, o);
                p3 += __shfl_xor_sync(0xffffffffu, p3, o);
            }
            if (lane == 0) {
                out[__ldg(g_eidx + j)]     = p0;
                out[__ldg(g_eidx + j + 1)] = p1;
                out[__ldg(g_eidx + j + 2)] = p2;
                out[__ldg(g_eidx + j + 3)] = p3;
                lmin = fminf(lmin, fminf(fminf(p0, p1), fminf(p2, p3)));
                lmax = fmaxf(lmax, fmaxf(fmaxf(p0, p1), fmaxf(p2, p3)));
            }
        }
        for (; j < end; j++) {
            int s0 = __ldg(g_srcs + j);
            uint2 a0 = __ldg((const uint2*)h + (size_t)s0 * 32 + lane);
            float p0 = dot4h(a0, d4);
#pragma unroll
            for (int o = 16; o; o >>= 1) p0 += __shfl_xor_sync(0xffffffffu, p0, o);
            if (lane == 0) {
                out[__ldg(g_eidx + j)] = p0;
                lmin = fminf(lmin, p0);
                lmax = fmaxf(lmax, p0);
            }
        }
    }

#pragma unroll
    for (int o = 16; o; o >>= 1) {
        lmin = fminf(lmin, __shfl_xor_sync(0xffffffffu, lmin, o));
        lmax = fmaxf(lmax, __shfl_xor_sync(0xffffffffu, lmax, o));
    }
    __shared__ float smin[8], smax[8];
    int wd = threadIdx.x >> 5;
    if (lane == 0) { smin[wd] = lmin; smax[wd] = lmax; }
    __syncthreads();
    if (threadIdx.x == 0) {
        float m0 = smin[0], m1 = smax[0];
#pragma unroll
        for (int i = 1; i < 8; i++) { m0 = fminf(m0, smin[i]); m1 = fmaxf(m1, smax[i]); }
        atomicMin(&g_mm[0], fenc(m0));
        atomicMax(&g_mm[1], fenc(m1));
    }
}

__global__ void k_norm(float4* __restrict__ out, int e4) {
    int i = blockIdx.x * blockDim.x + threadIdx.x;
    if (i >= e4) return;
    float mn = fdec(g_mm[0]);
    float inv = 1.0f / (fdec(g_mm[1]) - mn);
    float4 v = out[i];
    v.x = (v.x - mn) * inv; v.y = (v.y - mn) * inv;
    v.z = (v.z - mn) * inv; v.w = (v.w - mn) * inv;
    out[i] = v;
}

__global__ void k_norm1(float* __restrict__ out, int b, int e) {
    int i = b + blockIdx.x * blockDim.x + threadIdx.x;
    if (i >= e) return;
    float mn = fdec(g_mm[0]);
    float inv = 1.0f / (fdec(g_mm[1]) - mn);
    out[i] = (out[i] - mn) * inv;
}

// ---------------- launch ------------------------------------------------------
extern "C" void kernel_launch(void* const* d_in, const int* in_sizes, int n_in,
                              void* d_out, int out_size) {
    const float* x   = (const float*)d_in[0];
    const int*   src = (const int*)d_in[1];
    const int*   dst = (const int*)d_in[2];
    const float* Ws1 = (const float*)d_in[3];
    const float* Wn1 = (const float*)d_in[4];
    const float* b1  = (const float*)d_in[5];
    const float* Ws2 = (const float*)d_in[6];
    const float* Wn2 = (const float*)d_in[7];
    const float* b2  = (const float*)d_in[8];
    float* out = (float*)d_out;

    int n = in_sizes[0] / F;
    int e = in_sizes[1];
    int nb = (n + 127) >> 7;

    void *p_h1, *p_h2h, *p_agg, *p_W;
    cudaGetSymbolAddress(&p_h1, g_h1);
    cudaGetSymbolAddress(&p_h2h, g_h2h);
    cudaGetSymbolAddress(&p_agg, g_agg);
    cudaGetSymbolAddress(&p_W, g_Wimg);

    const int tpb = 256;
    const int SMEM = 1024 + 65536 + 65536 + 65536;   // 197,632 B
    cudaFuncSetAttribute(k_mma, cudaFuncAttributeMaxDynamicSharedMemorySize, SMEM);

    // CSR count (+fused W conversion, +scalar resets); g_cnt zero-invariant
    int countBlocks = (e + tpb - 1) / tpb;
    k_count<<<countBlocks + 64, tpb>>>(dst, e, countBlocks, Ws1, Wn1, Ws2, Wn2);
    k_offsets<<<(n + tpb - 1) / tpb, tpb>>>(n);
    k_fill<<<(e + tpb - 1) / tpb, tpb>>>(src, dst, e);

    int gatherBlocks = ((n * 32) + tpb - 1) / tpb;

    // layer 1: fp32 h1 out
    k_gather<<<gatherBlocks, tpb>>>(x, n);
    k_mma<<<nb, 256, SMEM>>>(x, (const float*)p_agg,
                             (const uint8_t*)p_W, b1, (float*)p_h1, (__half*)0, n);

    // layer 2: fp16 h2 out (score-only consumer)
    k_gather<<<gatherBlocks, tpb>>>((const float*)p_h1, n);
    k_mma<<<nb, 256, SMEM>>>((const float*)p_h1, (const float*)p_agg,
                             (const uint8_t*)((char*)p_W + 131072), b2,
                             (float*)0, (__half*)p_h2h, n);

    // CSR edge scores on fp16 rows + min/max + normalize
    k_score<<<gatherBlocks, tpb>>>((const __half*)p_h2h, out, n);
    int e4 = e >> 2;
    if (e4 > 0) k_norm<<<(e4 + tpb - 1) / tpb, tpb>>>((float4*)out, e4);
    if (e & 3) k_norm1<<<1, 256>>>(out, e4 * 4, e);
}

// round 15
// speedup vs baseline: 1.0636x; 1.0636x over previous
#include <cuda_runtime.h>
#include <cuda_bf16.h>
#include <cuda_fp16.h>
#include <math.h>
#include <stdint.h>

#define NMAX 100000
#define EMAX 1600000
#define F 128
#define NB_MAX 782

// ---------------- scratch (device globals) ----------------------------------
__device__ int   g_cnt[NMAX];            // zeroed invariant: k_offsets re-zeroes
__device__ int   g_off[NMAX];
__device__ int   g_end[NMAX];
__device__ int   g_pos[NMAX];
__device__ int   g_total;
__device__ int   g_srcs[EMAX];
__device__ int   g_eidx[EMAX];
__device__ float g_deg[NMAX];
__device__ float g_agg[(size_t)NMAX * F];
__device__ float g_h1[(size_t)NMAX * F];
__device__ __half g_h1h[(size_t)NMAX * F];   // fp16 copy of h1 (layer-2 gather)
__device__ __half g_h2h[(size_t)NMAX * F];   // layer-2 output, fp16 (score-only)
__device__ unsigned int g_mm[2];

// W images per layer (128KB): [self_hi 32K][neigh_hi 32K][self_lo 32K][neigh_lo 32K]
__device__ uint8_t g_Wimg[2 * 4 * 32768];

// ---------------- helpers -----------------------------------------------------
__device__ __forceinline__ unsigned fenc(float f) {
    unsigned u = __float_as_uint(f);
    return (u & 0x80000000u) ? ~u : (u | 0x80000000u);
}
__device__ __forceinline__ float fdec(unsigned u) {
    return __uint_as_float((u & 0x80000000u) ? (u ^ 0x80000000u) : ~u);
}
__device__ __forceinline__ uint32_t pkf(float a, float b) {
    __nv_bfloat162 t = __floats2bfloat162_rn(a, b);
    return *(uint32_t*)&t;
}
__device__ __forceinline__ void split2(float a, float b, uint32_t& hi, uint32_t& lo) {
    __nv_bfloat16 ha = __float2bfloat16(a), hb = __float2bfloat16(b);
    __nv_bfloat162 h2 = __halves2bfloat162(ha, hb);
    hi = *(uint32_t*)&h2;
    lo = pkf(a - __bfloat162float(ha), b - __bfloat162float(hb));
}
__device__ __forceinline__ uint32_t smem_u32(const void* p) {
    uint32_t a;
    asm("{ .reg .u64 t; cvta.to.shared.u64 t, %1; cvt.u32.u64 %0, t; }" : "=r"(a) : "l"(p));
    return a;
}
__device__ __forceinline__ void mb_init(uint32_t m, uint32_t c) {
    asm volatile("mbarrier.init.shared.b64 [%0], %1;" :: "r"(m), "r"(c) : "memory");
}
__device__ __forceinline__ void mb_extx(uint32_t m, uint32_t bytes) {
    asm volatile("mbarrier.arrive.expect_tx.shared.b64 _, [%0], %1;" :: "r"(m), "r"(bytes) : "memory");
}
__device__ __forceinline__ void mb_wait(uint32_t m, uint32_t parity) {
    asm volatile(
        "{\n\t.reg .pred P;\n\t"
        "WL_%=: mbarrier.try_wait.parity.shared::cta.b64 P, [%0], %1;\n\t"
        "@P bra WD_%=;\n\t bra WL_%=;\n\tWD_%=:\n\t}"
        :: "r"(m), "r"(parity) : "memory");
}
__device__ __forceinline__ void bulk_g2s(uint32_t dst, const void* src, uint32_t bytes, uint32_t mbar) {
    asm volatile("cp.async.bulk.shared::cta.global.mbarrier::complete_tx::bytes [%0], [%1], %2, [%3];"
                 :: "r"(dst), "l"(src), "r"(bytes), "r"(mbar) : "memory");
}
__device__ __forceinline__ void mma_bf16(float* d, const uint4 a, const uint2 b) {
    asm volatile(
        "mma.sync.aligned.m16n8k16.row.col.f32.bf16.bf16.f32 "
        "{%0,%1,%2,%3}, {%4,%5,%6,%7}, {%8,%9}, {%0,%1,%2,%3};"
        : "+f"(d[0]), "+f"(d[1]), "+f"(d[2]), "+f"(d[3])
        : "r"(a.x), "r"(a.y), "r"(a.z), "r"(a.w), "r"(b.x), "r"(b.y));
}
__device__ __forceinline__ float dot4h(uint2 a, uint2 b) {
    float2 ax = __half22float2(*(__half2*)&a.x);
    float2 ay = __half22float2(*(__half2*)&a.y);
    float2 bx = __half22float2(*(__half2*)&b.x);
    float2 by = __half22float2(*(__half2*)&b.y);
    return ax.x * bx.x + ax.y * bx.y + ay.x * by.x + ay.y * by.y;
}

// ---------------- CSR count + fused W conversion ------------------------------
__global__ void k_count(const int* __restrict__ dst, int e, int countBlocks,
                        const float* __restrict__ Ws1, const float* __restrict__ Wn1,
                        const float* __restrict__ Ws2, const float* __restrict__ Wn2) {
    if ((int)blockIdx.x >= countBlocks) {
        int idx = ((int)blockIdx.x - countBlocks) * blockDim.x + threadIdx.x;
        if (idx >= 4 * 8 * 16 * 32) return;
        int lane = idx & 31;
        int tn = (idx >> 5) & 15;
        int tk = (idx >> 9) & 7;
        int m = idx >> 12;
        const float* W = (m == 0) ? Ws1 : (m == 1) ? Wn1 : (m == 2) ? Ws2 : Wn2;
        int g = lane >> 2, t = lane & 3;
        int nn = tn * 8 + g;
        int k0 = tk * 16 + 2 * t;
        float w00 = __ldg(W + k0 * F + nn);
        float w01 = __ldg(W + (k0 + 1) * F + nn);
        float w10 = __ldg(W + (k0 + 8) * F + nn);
        float w11 = __ldg(W + (k0 + 9) * F + nn);
        uint2 hi, lo;
        split2(w00, w01, hi.x, lo.x);
        split2(w10, w11, hi.y, lo.y);
        int layer = m >> 1, which = m & 1;
        size_t base = (size_t)layer * 131072;
        size_t off = tk * 4096 + tn * 256 + lane * 8;
        *(uint2*)(g_Wimg + base + (size_t)which * 32768 + off) = hi;
        *(uint2*)(g_Wimg + base + 65536 + (size_t)which * 32768 + off) = lo;
        return;
    }
    if (threadIdx.x == 0 && blockIdx.x == 0) {
        g_total = 0;
        g_mm[0] = 0xFFFFFFFFu;
        g_mm[1] = 0u;
    }
    int i = blockIdx.x * blockDim.x + threadIdx.x;
    if (i < e) atomicAdd(&g_cnt[dst[i]], 1);
}

__global__ void k_offsets(int n) {
    __shared__ int wsum[8];
    __shared__ int sbase;
    int i = blockIdx.x * blockDim.x + threadIdx.x;
    int lane = threadIdx.x & 31, wid = threadIdx.x >> 5;
    int c = (i < n) ? g_cnt[i] : 0;
    int v = c;
#pragma unroll
    for (int o = 1; o < 32; o <<= 1) {
        int t = __shfl_up_sync(0xffffffffu, v, o);
        if (lane >= o) v += t;
    }
    if (lane == 31) wsum[wid] = v;
    __syncthreads();
    if (wid == 0) {
        int s = (lane < 8) ? wsum[lane] : 0;
#pragma unroll
        for (int o = 1; o < 8; o <<= 1) {
            int t = __shfl_up_sync(0xffffffffu, s, o);
            if (lane >= o) s += t;
        }
        if (lane < 8) wsum[lane] = s;
        if (lane == 7) sbase = atomicAdd(&g_total, s);
    }
    __syncthreads();
    if (i < n) {
        int excl = sbase + v - c + (wid ? wsum[wid - 1] : 0);
        g_off[i] = excl;
        g_pos[i] = excl;
        g_end[i] = excl + c;
        g_deg[i] = 1.0f / fmaxf((float)c, 1.0f);
        g_cnt[i] = 0;
    }
}

__global__ void k_fill(const int* __restrict__ src, const int* __restrict__ dst, int e) {
    int i = blockIdx.x * blockDim.x + threadIdx.x;
    if (i < e) {
        int p = atomicAdd(&g_pos[dst[i]], 1);
        g_srcs[p] = src[i];
        g_eidx[p] = i;
    }
}

// ---------------- gather (fp32 rows): warp per node, 4-way unroll ------------
__global__ void k_gather(const float* __restrict__ h, int n) {
    int w = (blockIdx.x * blockDim.x + threadIdx.x) >> 5;
    if (w >= n) return;
    int lane = threadIdx.x & 31;
    int beg = g_off[w];
    int end = g_end[w];
    float4 acc = make_float4(0.f, 0.f, 0.f, 0.f);
    int j = beg;
    for (; j + 3 < end; j += 4) {
        int s0 = __ldg(g_srcs + j);
        int s1 = __ldg(g_srcs + j + 1);
        int s2 = __ldg(g_srcs + j + 2);
        int s3 = __ldg(g_srcs + j + 3);
        float4 v0 = __ldg((const float4*)h + (size_t)s0 * 32 + lane);
        float4 v1 = __ldg((const float4*)h + (size_t)s1 * 32 + lane);
        float4 v2 = __ldg((const float4*)h + (size_t)s2 * 32 + lane);
        float4 v3 = __ldg((const float4*)h + (size_t)s3 * 32 + lane);
        acc.x += (v0.x + v1.x) + (v2.x + v3.x);
        acc.y += (v0.y + v1.y) + (v2.y + v3.y);
        acc.z += (v0.z + v1.z) + (v2.z + v3.z);
        acc.w += (v0.w + v1.w) + (v2.w + v3.w);
    }
    for (; j < end; j++) {
        int s0 = __ldg(g_srcs + j);
        float4 v0 = __ldg((const float4*)h + (size_t)s0 * 32 + lane);
        acc.x += v0.x; acc.y += v0.y; acc.z += v0.z; acc.w += v0.w;
    }
    float inv = g_deg[w];
    acc.x *= inv; acc.y *= inv; acc.z *= inv; acc.w *= inv;
    ((float4*)g_agg)[(size_t)w * 32 + lane] = acc;
}

// ---------------- gather (fp16 rows): warp per node, 4-way unroll ------------
__global__ void k_gatherH(const __half* __restrict__ h, int n) {
    int w = (blockIdx.x * blockDim.x + threadIdx.x) >> 5;
    if (w >= n) return;
    int lane = threadIdx.x & 31;
    int beg = g_off[w];
    int end = g_end[w];
    float4 acc = make_float4(0.f, 0.f, 0.f, 0.f);
    int j = beg;
    for (; j + 3 < end; j += 4) {
        int s0 = __ldg(g_srcs + j);
        int s1 = __ldg(g_srcs + j + 1);
        int s2 = __ldg(g_srcs + j + 2);
        int s3 = __ldg(g_srcs + j + 3);
        uint2 v0 = __ldg((const uint2*)h + (size_t)s0 * 32 + lane);
        uint2 v1 = __ldg((const uint2*)h + (size_t)s1 * 32 + lane);
        uint2 v2 = __ldg((const uint2*)h + (size_t)s2 * 32 + lane);
        uint2 v3 = __ldg((const uint2*)h + (size_t)s3 * 32 + lane);
#pragma unroll
        for (int q = 0; q < 4; q++) {
            uint2 v = (q == 0) ? v0 : (q == 1) ? v1 : (q == 2) ? v2 : v3;
            float2 a = __half22float2(*(__half2*)&v.x);
            float2 b = __half22float2(*(__half2*)&v.y);
            acc.x += a.x; acc.y += a.y; acc.z += b.x; acc.w += b.y;
        }
    }
    for (; j < end; j++) {
        int s0 = __ldg(g_srcs + j);
        uint2 v = __ldg((const uint2*)h + (size_t)s0 * 32 + lane);
        float2 a = __half22float2(*(__half2*)&v.x);
        float2 b = __half22float2(*(__half2*)&v.y);
        acc.x += a.x; acc.y += a.y; acc.z += b.x; acc.w += b.y;
    }
    float inv = g_deg[w];
    acc.x *= inv; acc.y *= inv; acc.z *= inv; acc.w *= inv;
    ((float4*)g_agg)[(size_t)w * 32 + lane] = acc;
}

// ---------------- conv cell helpers ------------------------------------------
__device__ __forceinline__ void conv_load(const float* __restrict__ src, int n,
                                          int base_row, int idx,
                                          float2& a00, float2& a01, float2& a10, float2& a11) {
    int lane = idx & 31;
    int tk = (idx >> 5) & 7;
    int tm = idx >> 8;
    int g = lane >> 2, t = lane & 3;
    int row0 = base_row + tm * 16 + g;
    int row1 = row0 + 8;
    int k0 = tk * 16 + 2 * t;
    a00 = make_float2(0.f, 0.f); a01 = a00; a10 = a00; a11 = a00;
    if (row0 < n) {
        a00 = __ldg((const float2*)(src + (size_t)row0 * F + k0));
        a01 = __ldg((const float2*)(src + (size_t)row0 * F + k0 + 8));
    }
    if (row1 < n) {
        a10 = __ldg((const float2*)(src + (size_t)row1 * F + k0));
        a11 = __ldg((const float2*)(src + (size_t)row1 * F + k0 + 8));
    }
}
__device__ __forceinline__ void conv_store(uint8_t* As, int idx,
                                           float2 a00, float2 a01, float2 a10, float2 a11) {
    int lane = idx & 31;
    int tk = (idx >> 5) & 7;
    int tm = idx >> 8;
    uint4 hi, lo;
    split2(a00.x, a00.y, hi.x, lo.x);
    split2(a10.x, a10.y, hi.y, lo.y);
    split2(a01.x, a01.y, hi.z, lo.z);
    split2(a11.x, a11.y, hi.w, lo.w);
    uint32_t off = tm * 4096 + tk * 512 + lane * 16;
    *(uint4*)(As + off) = hi;
    *(uint4*)(As + 32768 + off) = lo;
}
__device__ __forceinline__ void conv_tile(const float* __restrict__ src, int n,
                                          int base_row, uint8_t* As, int tid) {
#pragma unroll
    for (int u = 0; u < 8; u++) {
        float2 a00, a01, a10, a11;
        conv_load(src, n, base_row, tid + u * 256, a00, a01, a10, a11);
        conv_store(As, tid + u * 256, a00, a01, a10, a11);
    }
}

// ---------------- mma.sync GEMM, fully fused ---------------------------------
// hout (fp32) and/or houtH (fp16); layer 1 writes both, layer 2 only fp16.
__global__ void __launch_bounds__(256, 1)
k_mma(const float* __restrict__ selfF, const float* __restrict__ neighF,
      const uint8_t* __restrict__ Wbase, const float* __restrict__ bias,
      float* __restrict__ hout, __half* __restrict__ houtH, int n) {
    extern __shared__ __align__(128) uint8_t sm[];
    const uint32_t WOFF = 1024, A0OFF = 1024 + 65536, A1OFF = A0OFF + 65536;
    const int tid = threadIdx.x;
    const int lane = tid & 31, wid = tid >> 5;
    const int warp_m = wid >> 2, warp_n = wid & 3;
    const size_t b = blockIdx.x;
    const int base_row = (int)b * 128;
    uint32_t sb = smem_u32(sm);

    if (tid == 0) {
        mb_init(sb + 0, 1);
        asm volatile("fence.proxy.async.shared::cta;" ::: "memory");
    }
    __syncthreads();
    if (tid == 0) {
        mb_extx(sb + 0, 65536);
        bulk_g2s(sb + WOFF, Wbase, 65536, sb + 0);       // self_hi + neigh_hi
    }
    conv_tile(selfF, n, base_row, sm + A0OFF, tid);
    __syncthreads();
    mb_wait(sb + 0, 0);

    const uint8_t* WhiS = sm + WOFF;
    const uint8_t* WhiN = sm + WOFF + 32768;
    const uint8_t* WloS = Wbase + 65536;                 // global, L2-hot
    const uint8_t* WloN = Wbase + 98304;

    float acc[4][4][4];
#pragma unroll
    for (int i = 0; i < 4; i++)
#pragma unroll
        for (int j = 0; j < 4; j++)
#pragma unroll
            for (int c = 0; c < 4; c++) acc[i][j][c] = 0.f;

    // ---- phase 0 (self), neigh conversion pipelined in ----
#pragma unroll
    for (int tk = 0; tk < 8; tk++) {
        float2 c00, c01, c10, c11;
        conv_load(neighF, n, base_row, tid + tk * 256, c00, c01, c10, c11);

        uint4 af[4];
#pragma unroll
        for (int i = 0; i < 4; i++)
            af[i] = *(const uint4*)(sm + A0OFF + (warp_m * 4 + i) * 4096 + tk * 512 + lane * 16);
        {
            uint2 bf[4];
#pragma unroll
            for (int j = 0; j < 4; j++)
                bf[j] = *(const uint2*)(WhiS + tk * 4096 + (warp_n * 4 + j) * 256 + lane * 8);
#pragma unroll
            for (int i = 0; i < 4; i++)
#pragma unroll
                for (int j = 0; j < 4; j++)
                    mma_bf16(acc[i][j], af[i], bf[j]);
        }
        {
            uint2 bf[4];
#pragma unroll
            for (int j = 0; j < 4; j++)
                bf[j] = __ldg((const uint2*)(WloS + tk * 4096 + (warp_n * 4 + j) * 256 + lane * 8));
#pragma unroll
            for (int i = 0; i < 4; i++)
#pragma unroll
                for (int j = 0; j < 4; j++)
                    mma_bf16(acc[i][j], af[i], bf[j]);
        }
        conv_store(sm + A1OFF, tid + tk * 256, c00, c01, c10, c11);
    }
    // lo(self) x Whi(self)
#pragma unroll
    for (int tk = 0; tk < 8; tk++) {
        uint4 af[4];
        uint2 bf[4];
#pragma unroll
        for (int i = 0; i < 4; i++)
            af[i] = *(const uint4*)(sm + A0OFF + 32768 + (warp_m * 4 + i) * 4096 + tk * 512 + lane * 16);
#pragma unroll
        for (int j = 0; j < 4; j++)
            bf[j] = *(const uint2*)(WhiS + tk * 4096 + (warp_n * 4 + j) * 256 + lane * 8);
#pragma unroll
        for (int i = 0; i < 4; i++)
#pragma unroll
            for (int j = 0; j < 4; j++)
                mma_bf16(acc[i][j], af[i], bf[j]);
    }

    __syncthreads();                                     // A1 complete

    // ---- phase 1 (neigh) ----
#pragma unroll
    for (int tk = 0; tk < 8; tk++) {
        uint4 af[4];
#pragma unroll
        for (int i = 0; i < 4; i++)
            af[i] = *(const uint4*)(sm + A1OFF + (warp_m * 4 + i) * 4096 + tk * 512 + lane * 16);
        {
            uint2 bf[4];
#pragma unroll
            for (int j = 0; j < 4; j++)
                bf[j] = *(const uint2*)(WhiN + tk * 4096 + (warp_n * 4 + j) * 256 + lane * 8);
#pragma unroll
            for (int i = 0; i < 4; i++)
#pragma unroll
                for (int j = 0; j < 4; j++)
                    mma_bf16(acc[i][j], af[i], bf[j]);
        }
        {
            uint2 bf[4];
#pragma unroll
            for (int j = 0; j < 4; j++)
                bf[j] = __ldg((const uint2*)(WloN + tk * 4096 + (warp_n * 4 + j) * 256 + lane * 8));
#pragma unroll
            for (int i = 0; i < 4; i++)
#pragma unroll
                for (int j = 0; j < 4; j++)
                    mma_bf16(acc[i][j], af[i], bf[j]);
        }
    }
#pragma unroll
    for (int tk = 0; tk < 8; tk++) {
        uint4 af[4];
        uint2 bf[4];
#pragma unroll
        for (int i = 0; i < 4; i++)
            af[i] = *(const uint4*)(sm + A1OFF + 32768 + (warp_m * 4 + i) * 4096 + tk * 512 + lane * 16);
#pragma unroll
        for (int j = 0; j < 4; j++)
            bf[j] = *(const uint2*)(WhiN + tk * 4096 + (warp_n * 4 + j) * 256 + lane * 8);
#pragma unroll
        for (int i = 0; i < 4; i++)
#pragma unroll
            for (int j = 0; j < 4; j++)
                mma_bf16(acc[i][j], af[i], bf[j]);
    }

    // ---- epilogue: bias; fp32 and/or fp16 out ----
    const int g = lane >> 2, t = lane & 3;
#pragma unroll
    for (int i = 0; i < 4; i++) {
        int tm = warp_m * 4 + i;
        int row0 = base_row + tm * 16 + g;
        int row1 = row0 + 8;
#pragma unroll
        for (int j = 0; j < 4; j++) {
            int nb8 = (warp_n * 4 + j) * 8 + 2 * t;
            float2 bv = __ldg((const float2*)(bias + nb8));
            float c0 = acc[i][j][0] + bv.x, c1 = acc[i][j][1] + bv.y;
            float c2 = acc[i][j][2] + bv.x, c3 = acc[i][j][3] + bv.y;
            if (hout) {
                if (row0 < n) *(float2*)(hout + (size_t)row0 * F + nb8) = make_float2(c0, c1);
                if (row1 < n) *(float2*)(hout + (size_t)row1 * F + nb8) = make_float2(c2, c3);
            }
            if (houtH) {
                if (row0 < n) *(__half2*)(houtH + (size_t)row0 * F + nb8) = __floats2half2_rn(c0, c1);
                if (row1 < n) *(__half2*)(houtH + (size_t)row1 * F + nb8) = __floats2half2_rn(c2, c3);
            }
        }
    }
}

// ---------------- CSR edge scores on fp16 rows: warp per node ----------------
__global__ void k_score(const __half* __restrict__ h, float* __restrict__ out, int n) {
    int w = (blockIdx.x * blockDim.x + threadIdx.x) >> 5;
    int lane = threadIdx.x & 31;
    float lmin = 3.402823466e38f;
    float lmax = -3.402823466e38f;

    if (w < n) {
        int beg = g_off[w];
        int end = g_end[w];
        uint2 d4 = __ldg((const uint2*)h + (size_t)w * 32 + lane);   // 4 halves
        int j = beg;
        for (; j + 3 < end; j += 4) {
            int s0 = __ldg(g_srcs + j);
            int s1 = __ldg(g_srcs + j + 1);
            int s2 = __ldg(g_srcs + j + 2);
            int s3 = __ldg(g_srcs + j + 3);
            uint2 a0 = __ldg((const uint2*)h + (size_t)s0 * 32 + lane);
            uint2 a1 = __ldg((const uint2*)h + (size_t)s1 * 32 + lane);
            uint2 a2 = __ldg((const uint2*)h + (size_t)s2 * 32 + lane);
            uint2 a3 = __ldg((const uint2*)h + (size_t)s3 * 32 + lane);
            float p0 = dot4h(a0, d4);
            float p1 = dot4h(a1, d4);
            float p2 = dot4h(a2, d4);
            float p3 = dot4h(a3, d4);
#pragma unroll
            for (int o = 16; o; o >>= 1) {
                p0 += __shfl_xor_sync(0xffffffffu, p0, o);
                p1 += __shfl_xor_sync(0xffffffffu, p1, o);
                p2 += __shfl_xor_sync(0xffffffffu, p2, o);
                p3 += __shfl_xor_sync(0xffffffffu, p3, o);
            }
            if (lane == 0) {
                out[__ldg(g_eidx + j)]     = p0;
                out[__ldg(g_eidx + j + 1)] = p1;
                out[__ldg(g_eidx + j + 2)] = p2;
                out[__ldg(g_eidx + j + 3)] = p3;
                lmin = fminf(lmin, fminf(fminf(p0, p1), fminf(p2, p3)));
                lmax = fmaxf(lmax, fmaxf(fmaxf(p0, p1), fmaxf(p2, p3)));
            }
        }
        for (; j < end; j++) {
            int s0 = __ldg(g_srcs + j);
            uint2 a0 = __ldg((const uint2*)h + (size_t)s0 * 32 + lane);
            float p0 = dot4h(a0, d4);
#pragma unroll
            for (int o = 16; o; o >>= 1) p0 += __shfl_xor_sync(0xffffffffu, p0, o);
            if (lane == 0) {
                out[__ldg(g_eidx + j)] = p0;
                lmin = fminf(lmin, p0);
                lmax = fmaxf(lmax, p0);
            }
        }
    }

#pragma unroll
    for (int o = 16; o; o >>= 1) {
        lmin = fminf(lmin, __shfl_xor_sync(0xffffffffu, lmin, o));
        lmax = fmaxf(lmax, __shfl_xor_sync(0xffffffffu, lmax, o));
    }
    __shared__ float smin[8], smax[8];
    int wd = threadIdx.x >> 5;
    if (lane == 0) { smin[wd] = lmin; smax[wd] = lmax; }
    __syncthreads();
    if (threadIdx.x == 0) {
        float m0 = smin[0], m1 = smax[0];
#pragma unroll
        for (int i = 1; i < 8; i++) { m0 = fminf(m0, smin[i]); m1 = fmaxf(m1, smax[i]); }
        atomicMin(&g_mm[0], fenc(m0));
        atomicMax(&g_mm[1], fenc(m1));
    }
}

__global__ void k_norm(float4* __restrict__ out, int e4) {
    int i = blockIdx.x * blockDim.x + threadIdx.x;
    if (i >= e4) return;
    float mn = fdec(g_mm[0]);
    float inv = 1.0f / (fdec(g_mm[1]) - mn);
    float4 v = out[i];
    v.x = (v.x - mn) * inv; v.y = (v.y - mn) * inv;
    v.z = (v.z - mn) * inv; v.w = (v.w - mn) * inv;
    out[i] = v;
}

__global__ void k_norm1(float* __restrict__ out, int b, int e) {
    int i = b + blockIdx.x * blockDim.x + threadIdx.x;
    if (i >= e) return;
    float mn = fdec(g_mm[0]);
    float inv = 1.0f / (fdec(g_mm[1]) - mn);
    out[i] = (out[i] - mn) * inv;
}

// ---------------- launch ------------------------------------------------------
extern "C" void kernel_launch(void* const* d_in, const int* in_sizes, int n_in,
                              void* d_out, int out_size) {
    const float* x   = (const float*)d_in[0];
    const int*   src = (const int*)d_in[1];
    const int*   dst = (const int*)d_in[2];
    const float* Ws1 = (const float*)d_in[3];
    const float* Wn1 = (const float*)d_in[4];
    const float* b1  = (const float*)d_in[5];
    const float* Ws2 = (const float*)d_in[6];
    const float* Wn2 = (const float*)d_in[7];
    const float* b2  = (const float*)d_in[8];
    float* out = (float*)d_out;

    int n = in_sizes[0] / F;
    int e = in_sizes[1];
    int nb = (n + 127) >> 7;

    void *p_h1, *p_h1h, *p_h2h, *p_agg, *p_W;
    cudaGetSymbolAddress(&p_h1, g_h1);
    cudaGetSymbolAddress(&p_h1h, g_h1h);
    cudaGetSymbolAddress(&p_h2h, g_h2h);
    cudaGetSymbolAddress(&p_agg, g_agg);
    cudaGetSymbolAddress(&p_W, g_Wimg);

    const int tpb = 256;
    const int SMEM = 1024 + 65536 + 65536 + 65536;   // 197,632 B
    cudaFuncSetAttribute(k_mma, cudaFuncAttributeMaxDynamicSharedMemorySize, SMEM);

    // CSR count (+fused W conversion, +scalar resets); g_cnt zero-invariant
    int countBlocks = (e + tpb - 1) / tpb;
    k_count<<<countBlocks + 64, tpb>>>(dst, e, countBlocks, Ws1, Wn1, Ws2, Wn2);
    k_offsets<<<(n + tpb - 1) / tpb, tpb>>>(n);
    k_fill<<<(e + tpb - 1) / tpb, tpb>>>(src, dst, e);

    int gatherBlocks = ((n * 32) + tpb - 1) / tpb;

    // layer 1: gather x (fp32); h1 out in fp32 + fp16
    k_gather<<<gatherBlocks, tpb>>>(x, n);
    k_mma<<<nb, 256, SMEM>>>(x, (const float*)p_agg,
                             (const uint8_t*)p_W, b1,
                             (float*)p_h1, (__half*)p_h1h, n);

    // layer 2: gather h1 (fp16, half the bytes); h2 out fp16 only
    k_gatherH<<<gatherBlocks, tpb>>>((const __half*)p_h1h, n);
    k_mma<<<nb, 256, SMEM>>>((const float*)p_h1, (const float*)p_agg,
                             (const uint8_t*)((char*)p_W + 131072), b2,
                             (float*)0, (__half*)p_h2h, n);

    // CSR edge scores on fp16 rows + min/max + normalize
    k_score<<<gatherBlocks, tpb>>>((const __half*)p_h2h, out, n);
    int e4 = e >> 2;
    if (e4 > 0) k_norm<<<(e4 + tpb - 1) / tpb, tpb>>>((float4*)out, e4);
    if (e & 3) k_norm1<<<1, 256>>>(out, e4 * 4, e);
}

// round 16
// speedup vs baseline: 1.0827x; 1.0179x over previous
#include <cuda_runtime.h>
#include <cuda_bf16.h>
#include <cuda_fp16.h>
#include <math.h>
#include <stdint.h>

#define NMAX 100000
#define EMAX 1600000
#define F 128
#define NB_MAX 782

// ---------------- scratch (device globals) ----------------------------------
__device__ int   g_cnt[NMAX];            // zeroed invariant: k_offsets re-zeroes
__device__ int   g_off[NMAX];
__device__ int   g_end[NMAX];
__device__ int   g_pos[NMAX];
__device__ int   g_total;
__device__ int   g_srcs[EMAX];
__device__ int   g_eidx[EMAX];
__device__ float g_deg[NMAX];
__device__ float g_agg[(size_t)NMAX * F];
__device__ float g_h1[(size_t)NMAX * F];
__device__ __half g_xh[(size_t)NMAX * F];    // fp16 copy of x (layer-1 gather)
__device__ __half g_h1h[(size_t)NMAX * F];   // fp16 copy of h1 (layer-2 gather)
__device__ __half g_h2h[(size_t)NMAX * F];   // layer-2 output, fp16 (score-only)
__device__ unsigned int g_mm[2];

// W images per layer (128KB): [self_hi 32K][neigh_hi 32K][self_lo 32K][neigh_lo 32K]
__device__ uint8_t g_Wimg[2 * 4 * 32768];

// ---------------- helpers -----------------------------------------------------
__device__ __forceinline__ unsigned fenc(float f) {
    unsigned u = __float_as_uint(f);
    return (u & 0x80000000u) ? ~u : (u | 0x80000000u);
}
__device__ __forceinline__ float fdec(unsigned u) {
    return __uint_as_float((u & 0x80000000u) ? (u ^ 0x80000000u) : ~u);
}
__device__ __forceinline__ uint32_t pkf(float a, float b) {
    __nv_bfloat162 t = __floats2bfloat162_rn(a, b);
    return *(uint32_t*)&t;
}
__device__ __forceinline__ void split2(float a, float b, uint32_t& hi, uint32_t& lo) {
    __nv_bfloat16 ha = __float2bfloat16(a), hb = __float2bfloat16(b);
    __nv_bfloat162 h2 = __halves2bfloat162(ha, hb);
    hi = *(uint32_t*)&h2;
    lo = pkf(a - __bfloat162float(ha), b - __bfloat162float(hb));
}
__device__ __forceinline__ uint32_t smem_u32(const void* p) {
    uint32_t a;
    asm("{ .reg .u64 t; cvta.to.shared.u64 t, %1; cvt.u32.u64 %0, t; }" : "=r"(a) : "l"(p));
    return a;
}
__device__ __forceinline__ void mb_init(uint32_t m, uint32_t c) {
    asm volatile("mbarrier.init.shared.b64 [%0], %1;" :: "r"(m), "r"(c) : "memory");
}
__device__ __forceinline__ void mb_extx(uint32_t m, uint32_t bytes) {
    asm volatile("mbarrier.arrive.expect_tx.shared.b64 _, [%0], %1;" :: "r"(m), "r"(bytes) : "memory");
}
__device__ __forceinline__ void mb_wait(uint32_t m, uint32_t parity) {
    asm volatile(
        "{\n\t.reg .pred P;\n\t"
        "WL_%=: mbarrier.try_wait.parity.shared::cta.b64 P, [%0], %1;\n\t"
        "@P bra WD_%=;\n\t bra WL_%=;\n\tWD_%=:\n\t}"
        :: "r"(m), "r"(parity) : "memory");
}
__device__ __forceinline__ void bulk_g2s(uint32_t dst, const void* src, uint32_t bytes, uint32_t mbar) {
    asm volatile("cp.async.bulk.shared::cta.global.mbarrier::complete_tx::bytes [%0], [%1], %2, [%3];"
                 :: "r"(dst), "l"(src), "r"(bytes), "r"(mbar) : "memory");
}
__device__ __forceinline__ void mma_bf16(float* d, const uint4 a, const uint2 b) {
    asm volatile(
        "mma.sync.aligned.m16n8k16.row.col.f32.bf16.bf16.f32 "
        "{%0,%1,%2,%3}, {%4,%5,%6,%7}, {%8,%9}, {%0,%1,%2,%3};"
        : "+f"(d[0]), "+f"(d[1]), "+f"(d[2]), "+f"(d[3])
        : "r"(a.x), "r"(a.y), "r"(a.z), "r"(a.w), "r"(b.x), "r"(b.y));
}
__device__ __forceinline__ float dot4h(uint2 a, uint2 b) {
    float2 ax = __half22float2(*(__half2*)&a.x);
    float2 ay = __half22float2(*(__half2*)&a.y);
    float2 bx = __half22float2(*(__half2*)&b.x);
    float2 by = __half22float2(*(__half2*)&b.y);
    return ax.x * bx.x + ax.y * bx.y + ay.x * by.x + ay.y * by.y;
}

// ---------------- CSR count + fused W conversion + fused x->fp16 -------------
__global__ void k_count(const int* __restrict__ dst, int e, int countBlocks,
                        const float* __restrict__ x, int n,
                        const float* __restrict__ Ws1, const float* __restrict__ Wn1,
                        const float* __restrict__ Ws2, const float* __restrict__ Wn2) {
    int bb = (int)blockIdx.x;
    if (bb >= countBlocks + 64) {
        // ---- x -> fp16 conversion (n*32 float4 cells) ----
        int idx = (bb - countBlocks - 64) * blockDim.x + threadIdx.x;
        if (idx >= n * 32) return;
        float4 v = __ldg((const float4*)x + idx);
        uint2 o;
        *(__half2*)&o.x = __floats2half2_rn(v.x, v.y);
        *(__half2*)&o.y = __floats2half2_rn(v.z, v.w);
        ((uint2*)g_xh)[idx] = o;
        return;
    }
    if (bb >= countBlocks) {
        // ---- W fragment conversion (64 blocks) ----
        int idx = (bb - countBlocks) * blockDim.x + threadIdx.x;
        if (idx >= 4 * 8 * 16 * 32) return;
        int lane = idx & 31;
        int tn = (idx >> 5) & 15;
        int tk = (idx >> 9) & 7;
        int m = idx >> 12;
        const float* W = (m == 0) ? Ws1 : (m == 1) ? Wn1 : (m == 2) ? Ws2 : Wn2;
        int g = lane >> 2, t = lane & 3;
        int nn = tn * 8 + g;
        int k0 = tk * 16 + 2 * t;
        float w00 = __ldg(W + k0 * F + nn);
        float w01 = __ldg(W + (k0 + 1) * F + nn);
        float w10 = __ldg(W + (k0 + 8) * F + nn);
        float w11 = __ldg(W + (k0 + 9) * F + nn);
        uint2 hi, lo;
        split2(w00, w01, hi.x, lo.x);
        split2(w10, w11, hi.y, lo.y);
        int layer = m >> 1, which = m & 1;
        size_t base = (size_t)layer * 131072;
        size_t off = tk * 4096 + tn * 256 + lane * 8;
        *(uint2*)(g_Wimg + base + (size_t)which * 32768 + off) = hi;
        *(uint2*)(g_Wimg + base + 65536 + (size_t)which * 32768 + off) = lo;
        return;
    }
    if (threadIdx.x == 0 && bb == 0) {
        g_total = 0;
        g_mm[0] = 0xFFFFFFFFu;
        g_mm[1] = 0u;
    }
    int i = bb * blockDim.x + threadIdx.x;
    if (i < e) atomicAdd(&g_cnt[dst[i]], 1);
}

__global__ void k_offsets(int n) {
    __shared__ int wsum[8];
    __shared__ int sbase;
    int i = blockIdx.x * blockDim.x + threadIdx.x;
    int lane = threadIdx.x & 31, wid = threadIdx.x >> 5;
    int c = (i < n) ? g_cnt[i] : 0;
    int v = c;
#pragma unroll
    for (int o = 1; o < 32; o <<= 1) {
        int t = __shfl_up_sync(0xffffffffu, v, o);
        if (lane >= o) v += t;
    }
    if (lane == 31) wsum[wid] = v;
    __syncthreads();
    if (wid == 0) {
        int s = (lane < 8) ? wsum[lane] : 0;
#pragma unroll
        for (int o = 1; o < 8; o <<= 1) {
            int t = __shfl_up_sync(0xffffffffu, s, o);
            if (lane >= o) s += t;
        }
        if (lane < 8) wsum[lane] = s;
        if (lane == 7) sbase = atomicAdd(&g_total, s);
    }
    __syncthreads();
    if (i < n) {
        int excl = sbase + v - c + (wid ? wsum[wid - 1] : 0);
        g_off[i] = excl;
        g_pos[i] = excl;
        g_end[i] = excl + c;
        g_deg[i] = 1.0f / fmaxf((float)c, 1.0f);
        g_cnt[i] = 0;
    }
}

__global__ void k_fill(const int* __restrict__ src, const int* __restrict__ dst, int e) {
    int i = blockIdx.x * blockDim.x + threadIdx.x;
    if (i < e) {
        int p = atomicAdd(&g_pos[dst[i]], 1);
        g_srcs[p] = src[i];
        g_eidx[p] = i;
    }
}

// ---------------- gather (fp16 rows): warp per node, 4-way unroll ------------
__global__ void k_gatherH(const __half* __restrict__ h, int n) {
    int w = (blockIdx.x * blockDim.x + threadIdx.x) >> 5;
    if (w >= n) return;
    int lane = threadIdx.x & 31;
    int beg = g_off[w];
    int end = g_end[w];
    float4 acc = make_float4(0.f, 0.f, 0.f, 0.f);
    int j = beg;
    for (; j + 3 < end; j += 4) {
        int s0 = __ldg(g_srcs + j);
        int s1 = __ldg(g_srcs + j + 1);
        int s2 = __ldg(g_srcs + j + 2);
        int s3 = __ldg(g_srcs + j + 3);
        uint2 v0 = __ldg((const uint2*)h + (size_t)s0 * 32 + lane);
        uint2 v1 = __ldg((const uint2*)h + (size_t)s1 * 32 + lane);
        uint2 v2 = __ldg((const uint2*)h + (size_t)s2 * 32 + lane);
        uint2 v3 = __ldg((const uint2*)h + (size_t)s3 * 32 + lane);
#pragma unroll
        for (int q = 0; q < 4; q++) {
            uint2 v = (q == 0) ? v0 : (q == 1) ? v1 : (q == 2) ? v2 : v3;
            float2 a = __half22float2(*(__half2*)&v.x);
            float2 b = __half22float2(*(__half2*)&v.y);
            acc.x += a.x; acc.y += a.y; acc.z += b.x; acc.w += b.y;
        }
    }
    for (; j < end; j++) {
        int s0 = __ldg(g_srcs + j);
        uint2 v = __ldg((const uint2*)h + (size_t)s0 * 32 + lane);
        float2 a = __half22float2(*(__half2*)&v.x);
        float2 b = __half22float2(*(__half2*)&v.y);
        acc.x += a.x; acc.y += a.y; acc.z += b.x; acc.w += b.y;
    }
    float inv = g_deg[w];
    acc.x *= inv; acc.y *= inv; acc.z *= inv; acc.w *= inv;
    ((float4*)g_agg)[(size_t)w * 32 + lane] = acc;
}

// ---------------- conv cell helpers ------------------------------------------
__device__ __forceinline__ void conv_load(const float* __restrict__ src, int n,
                                          int base_row, int idx,
                                          float2& a00, float2& a01, float2& a10, float2& a11) {
    int lane = idx & 31;
    int tk = (idx >> 5) & 7;
    int tm = idx >> 8;
    int g = lane >> 2, t = lane & 3;
    int row0 = base_row + tm * 16 + g;
    int row1 = row0 + 8;
    int k0 = tk * 16 + 2 * t;
    a00 = make_float2(0.f, 0.f); a01 = a00; a10 = a00; a11 = a00;
    if (row0 < n) {
        a00 = __ldg((const float2*)(src + (size_t)row0 * F + k0));
        a01 = __ldg((const float2*)(src + (size_t)row0 * F + k0 + 8));
    }
    if (row1 < n) {
        a10 = __ldg((const float2*)(src + (size_t)row1 * F + k0));
        a11 = __ldg((const float2*)(src + (size_t)row1 * F + k0 + 8));
    }
}
__device__ __forceinline__ void conv_store(uint8_t* As, int idx,
                                           float2 a00, float2 a01, float2 a10, float2 a11) {
    int lane = idx & 31;
    int tk = (idx >> 5) & 7;
    int tm = idx >> 8;
    uint4 hi, lo;
    split2(a00.x, a00.y, hi.x, lo.x);
    split2(a10.x, a10.y, hi.y, lo.y);
    split2(a01.x, a01.y, hi.z, lo.z);
    split2(a11.x, a11.y, hi.w, lo.w);
    uint32_t off = tm * 4096 + tk * 512 + lane * 16;
    *(uint4*)(As + off) = hi;
    *(uint4*)(As + 32768 + off) = lo;
}
__device__ __forceinline__ void conv_tile(const float* __restrict__ src, int n,
                                          int base_row, uint8_t* As, int tid) {
#pragma unroll
    for (int u = 0; u < 8; u++) {
        float2 a00, a01, a10, a11;
        conv_load(src, n, base_row, tid + u * 256, a00, a01, a10, a11);
        conv_store(As, tid + u * 256, a00, a01, a10, a11);
    }
}

// ---------------- mma.sync GEMM, fully fused ---------------------------------
__global__ void __launch_bounds__(256, 1)
k_mma(const float* __restrict__ selfF, const float* __restrict__ neighF,
      const uint8_t* __restrict__ Wbase, const float* __restrict__ bias,
      float* __restrict__ hout, __half* __restrict__ houtH, int n) {
    extern __shared__ __align__(128) uint8_t sm[];
    const uint32_t WOFF = 1024, A0OFF = 1024 + 65536, A1OFF = A0OFF + 65536;
    const int tid = threadIdx.x;
    const int lane = tid & 31, wid = tid >> 5;
    const int warp_m = wid >> 2, warp_n = wid & 3;
    const size_t b = blockIdx.x;
    const int base_row = (int)b * 128;
    uint32_t sb = smem_u32(sm);

    if (tid == 0) {
        mb_init(sb + 0, 1);
        asm volatile("fence.proxy.async.shared::cta;" ::: "memory");
    }
    __syncthreads();
    if (tid == 0) {
        mb_extx(sb + 0, 65536);
        bulk_g2s(sb + WOFF, Wbase, 65536, sb + 0);       // self_hi + neigh_hi
    }
    conv_tile(selfF, n, base_row, sm + A0OFF, tid);
    __syncthreads();
    mb_wait(sb + 0, 0);

    const uint8_t* WhiS = sm + WOFF;
    const uint8_t* WhiN = sm + WOFF + 32768;
    const uint8_t* WloS = Wbase + 65536;                 // global, L2-hot
    const uint8_t* WloN = Wbase + 98304;

    float acc[4][4][4];
#pragma unroll
    for (int i = 0; i < 4; i++)
#pragma unroll
        for (int j = 0; j < 4; j++)
#pragma unroll
            for (int c = 0; c < 4; c++) acc[i][j][c] = 0.f;

    // ---- phase 0 (self), neigh conversion pipelined in ----
#pragma unroll
    for (int tk = 0; tk < 8; tk++) {
        float2 c00, c01, c10, c11;
        conv_load(neighF, n, base_row, tid + tk * 256, c00, c01, c10, c11);

        uint4 af[4];
#pragma unroll
        for (int i = 0; i < 4; i++)
            af[i] = *(const uint4*)(sm + A0OFF + (warp_m * 4 + i) * 4096 + tk * 512 + lane * 16);
        {
            uint2 bf[4];
#pragma unroll
            for (int j = 0; j < 4; j++)
                bf[j] = *(const uint2*)(WhiS + tk * 4096 + (warp_n * 4 + j) * 256 + lane * 8);
#pragma unroll
            for (int i = 0; i < 4; i++)
#pragma unroll
                for (int j = 0; j < 4; j++)
                    mma_bf16(acc[i][j], af[i], bf[j]);
        }
        {
            uint2 bf[4];
#pragma unroll
            for (int j = 0; j < 4; j++)
                bf[j] = __ldg((const uint2*)(WloS + tk * 4096 + (warp_n * 4 + j) * 256 + lane * 8));
#pragma unroll
            for (int i = 0; i < 4; i++)
#pragma unroll
                for (int j = 0; j < 4; j++)
                    mma_bf16(acc[i][j], af[i], bf[j]);
        }
        conv_store(sm + A1OFF, tid + tk * 256, c00, c01, c10, c11);
    }
    // lo(self) x Whi(self)
#pragma unroll
    for (int tk = 0; tk < 8; tk++) {
        uint4 af[4];
        uint2 bf[4];
#pragma unroll
        for (int i = 0; i < 4; i++)
            af[i] = *(const uint4*)(sm + A0OFF + 32768 + (warp_m * 4 + i) * 4096 + tk * 512 + lane * 16);
#pragma unroll
        for (int j = 0; j < 4; j++)
            bf[j] = *(const uint2*)(WhiS + tk * 4096 + (warp_n * 4 + j) * 256 + lane * 8);
#pragma unroll
        for (int i = 0; i < 4; i++)
#pragma unroll
            for (int j = 0; j < 4; j++)
                mma_bf16(acc[i][j], af[i], bf[j]);
    }

    __syncthreads();                                     // A1 complete

    // ---- phase 1 (neigh) ----
#pragma unroll
    for (int tk = 0; tk < 8; tk++) {
        uint4 af[4];
#pragma unroll
        for (int i = 0; i < 4; i++)
            af[i] = *(const uint4*)(sm + A1OFF + (warp_m * 4 + i) * 4096 + tk * 512 + lane * 16);
        {
            uint2 bf[4];
#pragma unroll
            for (int j = 0; j < 4; j++)
                bf[j] = *(const uint2*)(WhiN + tk * 4096 + (warp_n * 4 + j) * 256 + lane * 8);
#pragma unroll
            for (int i = 0; i < 4; i++)
#pragma unroll
                for (int j = 0; j < 4; j++)
                    mma_bf16(acc[i][j], af[i], bf[j]);
        }
        {
            uint2 bf[4];
#pragma unroll
            for (int j = 0; j < 4; j++)
                bf[j] = __ldg((const uint2*)(WloN + tk * 4096 + (warp_n * 4 + j) * 256 + lane * 8));
#pragma unroll
            for (int i = 0; i < 4; i++)
#pragma unroll
                for (int j = 0; j < 4; j++)
                    mma_bf16(acc[i][j], af[i], bf[j]);
        }
    }
#pragma unroll
    for (int tk = 0; tk < 8; tk++) {
        uint4 af[4];
        uint2 bf[4];
#pragma unroll
        for (int i = 0; i < 4; i++)
            af[i] = *(const uint4*)(sm + A1OFF + 32768 + (warp_m * 4 + i) * 4096 + tk * 512 + lane * 16);
#pragma unroll
        for (int j = 0; j < 4; j++)
            bf[j] = *(const uint2*)(WhiN + tk * 4096 + (warp_n * 4 + j) * 256 + lane * 8);
#pragma unroll
        for (int i = 0; i < 4; i++)
#pragma unroll
            for (int j = 0; j < 4; j++)
                mma_bf16(acc[i][j], af[i], bf[j]);
    }

    // ---- epilogue: bias; fp32 and/or fp16 out ----
    const int g = lane >> 2, t = lane & 3;
#pragma unroll
    for (int i = 0; i < 4; i++) {
        int tm = warp_m * 4 + i;
        int row0 = base_row + tm * 16 + g;
        int row1 = row0 + 8;
#pragma unroll
        for (int j = 0; j < 4; j++) {
            int nb8 = (warp_n * 4 + j) * 8 + 2 * t;
            float2 bv = __ldg((const float2*)(bias + nb8));
            float c0 = acc[i][j][0] + bv.x, c1 = acc[i][j][1] + bv.y;
            float c2 = acc[i][j][2] + bv.x, c3 = acc[i][j][3] + bv.y;
            if (hout) {
                if (row0 < n) *(float2*)(hout + (size_t)row0 * F + nb8) = make_float2(c0, c1);
                if (row1 < n) *(float2*)(hout + (size_t)row1 * F + nb8) = make_float2(c2, c3);
            }
            if (houtH) {
                if (row0 < n) *(__half2*)(houtH + (size_t)row0 * F + nb8) = __floats2half2_rn(c0, c1);
                if (row1 < n) *(__half2*)(houtH + (size_t)row1 * F + nb8) = __floats2half2_rn(c2, c3);
            }
        }
    }
}

// ---------------- CSR edge scores on fp16 rows: warp per node ----------------
__global__ void k_score(const __half* __restrict__ h, float* __restrict__ out, int n) {
    int w = (blockIdx.x * blockDim.x + threadIdx.x) >> 5;
    int lane = threadIdx.x & 31;
    float lmin = 3.402823466e38f;
    float lmax = -3.402823466e38f;

    if (w < n) {
        int beg = g_off[w];
        int end = g_end[w];
        uint2 d4 = __ldg((const uint2*)h + (size_t)w * 32 + lane);   // 4 halves
        int j = beg;
        for (; j + 3 < end; j += 4) {
            int s0 = __ldg(g_srcs + j);
            int s1 = __ldg(g_srcs + j + 1);
            int s2 = __ldg(g_srcs + j + 2);
            int s3 = __ldg(g_srcs + j + 3);
            uint2 a0 = __ldg((const uint2*)h + (size_t)s0 * 32 + lane);
            uint2 a1 = __ldg((const uint2*)h + (size_t)s1 * 32 + lane);
            uint2 a2 = __ldg((const uint2*)h + (size_t)s2 * 32 + lane);
            uint2 a3 = __ldg((const uint2*)h + (size_t)s3 * 32 + lane);
            float p0 = dot4h(a0, d4);
            float p1 = dot4h(a1, d4);
            float p2 = dot4h(a2, d4);
            float p3 = dot4h(a3, d4);
#pragma unroll
            for (int o = 16; o; o >>= 1) {
                p0 += __shfl_xor_sync(0xffffffffu, p0, o);
                p1 += __shfl_xor_sync(0xffffffffu, p1, o);
                p2 += __shfl_xor_sync(0xffffffffu, p2, o);
                p3 += __shfl_xor_sync(0xffffffffu, p3, o);
            }
            if (lane == 0) {
                out[__ldg(g_eidx + j)]     = p0;
                out[__ldg(g_eidx + j + 1)] = p1;
                out[__ldg(g_eidx + j + 2)] = p2;
                out[__ldg(g_eidx + j + 3)] = p3;
                lmin = fminf(lmin, fminf(fminf(p0, p1), fminf(p2, p3)));
                lmax = fmaxf(lmax, fmaxf(fmaxf(p0, p1), fmaxf(p2, p3)));
            }
        }
        for (; j < end; j++) {
            int s0 = __ldg(g_srcs + j);
            uint2 a0 = __ldg((const uint2*)h + (size_t)s0 * 32 + lane);
            float p0 = dot4h(a0, d4);
#pragma unroll
            for (int o = 16; o; o >>= 1) p0 += __shfl_xor_sync(0xffffffffu, p0, o);
            if (lane == 0) {
                out[__ldg(g_eidx + j)] = p0;
                lmin = fminf(lmin, p0);
                lmax = fmaxf(lmax, p0);
            }
        }
    }

#pragma unroll
    for (int o = 16; o; o >>= 1) {
        lmin = fminf(lmin, __shfl_xor_sync(0xffffffffu, lmin, o));
        lmax = fmaxf(lmax, __shfl_xor_sync(0xffffffffu, lmax, o));
    }
    __shared__ float smin[8], smax[8];
    int wd = threadIdx.x >> 5;
    if (lane == 0) { smin[wd] = lmin; smax[wd] = lmax; }
    __syncthreads();
    if (threadIdx.x == 0) {
        float m0 = smin[0], m1 = smax[0];
#pragma unroll
        for (int i = 1; i < 8; i++) { m0 = fminf(m0, smin[i]); m1 = fmaxf(m1, smax[i]); }
        atomicMin(&g_mm[0], fenc(m0));
        atomicMax(&g_mm[1], fenc(m1));
    }
}

__global__ void k_norm(float4* __restrict__ out, int e4) {
    int i = blockIdx.x * blockDim.x + threadIdx.x;
    if (i >= e4) return;
    float mn = fdec(g_mm[0]);
    float inv = 1.0f / (fdec(g_mm[1]) - mn);
    float4 v = out[i];
    v.x = (v.x - mn) * inv; v.y = (v.y - mn) * inv;
    v.z = (v.z - mn) * inv; v.w = (v.w - mn) * inv;
    out[i] = v;
}

__global__ void k_norm1(float* __restrict__ out, int b, int e) {
    int i = b + blockIdx.x * blockDim.x + threadIdx.x;
    if (i >= e) return;
    float mn = fdec(g_mm[0]);
    float inv = 1.0f / (fdec(g_mm[1]) - mn);
    out[i] = (out[i] - mn) * inv;
}

// ---------------- launch ------------------------------------------------------
extern "C" void kernel_launch(void* const* d_in, const int* in_sizes, int n_in,
                              void* d_out, int out_size) {
    const float* x   = (const float*)d_in[0];
    const int*   src = (const int*)d_in[1];
    const int*   dst = (const int*)d_in[2];
    const float* Ws1 = (const float*)d_in[3];
    const float* Wn1 = (const float*)d_in[4];
    const float* b1  = (const float*)d_in[5];
    const float* Ws2 = (const float*)d_in[6];
    const float* Wn2 = (const float*)d_in[7];
    const float* b2  = (const float*)d_in[8];
    float* out = (float*)d_out;

    int n = in_sizes[0] / F;
    int e = in_sizes[1];
    int nb = (n + 127) >> 7;

    void *p_h1, *p_xh, *p_h1h, *p_h2h, *p_agg, *p_W;
    cudaGetSymbolAddress(&p_h1, g_h1);
    cudaGetSymbolAddress(&p_xh, g_xh);
    cudaGetSymbolAddress(&p_h1h, g_h1h);
    cudaGetSymbolAddress(&p_h2h, g_h2h);
    cudaGetSymbolAddress(&p_agg, g_agg);
    cudaGetSymbolAddress(&p_W, g_Wimg);

    const int tpb = 256;
    const int SMEM = 1024 + 65536 + 65536 + 65536;   // 197,632 B
    cudaFuncSetAttribute(k_mma, cudaFuncAttributeMaxDynamicSharedMemorySize, SMEM);

    // CSR count (+W conversion, +x->fp16, +scalar resets); g_cnt zero-invariant
    int countBlocks = (e + tpb - 1) / tpb;
    int convxBlocks = (n * 32 + tpb - 1) / tpb;
    k_count<<<countBlocks + 64 + convxBlocks, tpb>>>(dst, e, countBlocks, x, n,
                                                     Ws1, Wn1, Ws2, Wn2);
    k_offsets<<<(n + tpb - 1) / tpb, tpb>>>(n);
    k_fill<<<(e + tpb - 1) / tpb, tpb>>>(src, dst, e);

    int gatherBlocks = ((n * 32) + tpb - 1) / tpb;

    // layer 1: gather x (fp16 rows); h1 out in fp32 + fp16
    k_gatherH<<<gatherBlocks, tpb>>>((const __half*)p_xh, n);
    k_mma<<<nb, 256, SMEM>>>(x, (const float*)p_agg,
                             (const uint8_t*)p_W, b1,
                             (float*)p_h1, (__half*)p_h1h, n);

    // layer 2: gather h1 (fp16 rows); h2 out fp16 only
    k_gatherH<<<gatherBlocks, tpb>>>((const __half*)p_h1h, n);
    k_mma<<<nb, 256, SMEM>>>((const float*)p_h1, (const float*)p_agg,
                             (const uint8_t*)((char*)p_W + 131072), b2,
                             (float*)0, (__half*)p_h2h, n);

    // CSR edge scores on fp16 rows + min/max + normalize
    k_score<<<gatherBlocks, tpb>>>((const __half*)p_h2h, out, n);
    int e4 = e >> 2;
    if (e4 > 0) k_norm<<<(e4 + tpb - 1) / tpb, tpb>>>((float4*)out, e4);
    if (e & 3) k_norm1<<<1, 256>>>(out, e4 * 4, e);
}